// round 4
// baseline (speedup 1.0000x reference)
#include <cuda_runtime.h>
#include <cuda_fp16.h>

// Sinkhorn OT loss: B=1024, N=M=256, eps=0.1, 100 iters.
// One CTA per batch. K = exp(-10*C)*16 cached in SMEM as fp16, row pitch
// 264 halves (528 B): 16B-aligned rows (LDS.128 row pass, conflict-free)
// and conflict-free column walks. u/v/a/b fp32 SMEM. Final cost pass
// recomputes exact fp32 K from C.

#define BATCH   1024
#define DIM     256
#define MAX_IT  100
#define EPS_DIV 1e-8f
#define KSCALE      16.0f
#define INV_KSCALE  0.0625f
#define SK      264   // HALF elements per row (528 bytes; 132 words)

#define SMEM_BYTES (DIM * SK * 2 + 4 * DIM * 4 + 128)

__device__ float g_partial[BATCH];

__device__ __forceinline__ float block_sum256(float val, float* red, int tid) {
    #pragma unroll
    for (int o = 16; o > 0; o >>= 1)
        val += __shfl_xor_sync(0xffffffffu, val, o);
    if ((tid & 31) == 0) red[tid >> 5] = val;
    __syncthreads();
    float total = 0.f;
    #pragma unroll
    for (int w = 0; w < 8; ++w) total += red[w];
    __syncthreads();
    return total;
}

extern "C" __global__ void __launch_bounds__(256)
sinkhorn_kernel(const float* __restrict__ C,
                const float* __restrict__ mp,
                const float* __restrict__ mt)
{
    extern __shared__ unsigned char smem_raw[];
    __half* Kh  = (__half*)smem_raw;                       // 256 rows * 264 halves
    float*  u_s = (float*)(smem_raw + DIM * SK * 2);
    float*  v_s = u_s + DIM;
    float*  a_s = v_s + DIM;
    float*  b_s = a_s + DIM;
    float*  red = b_s + DIM;                               // 8 floats used

    const int b   = blockIdx.x;
    const int tid = threadIdx.x;
    const float* Cb = C + (size_t)b * (DIM * DIM);
    const float4* C4 = (const float4*)Cb;

    // ---- Phase 1: K = exp(-10C)*16 -> fp16 SMEM -------------------------
    for (int i = tid; i < (DIM * DIM / 4); i += 256) {
        float4 c = C4[i];
        int r   = i >> 6;            // row   (i*4)/256
        int col = (i & 63) << 2;     // col base
        __half2 h0 = __floats2half2_rn(__expf(-10.f * c.x) * KSCALE,
                                       __expf(-10.f * c.y) * KSCALE);
        __half2 h1 = __floats2half2_rn(__expf(-10.f * c.z) * KSCALE,
                                       __expf(-10.f * c.w) * KSCALE);
        __half2* dst = (__half2*)(Kh + r * SK + col);
        dst[0] = h0;
        dst[1] = h1;
    }

    // ---- Phase 2: normalize masses, init u,v ----------------------------
    float mpv = mp[b * DIM + tid];
    float mtv = mt[b * DIM + tid];
    __syncthreads();   // Kh writes done before iterations; red ready
    float smp = block_sum256(mpv, red, tid);
    float smt = block_sum256(mtv, red, tid);
    a_s[tid] = mpv / (smp + EPS_DIV);
    b_s[tid] = mtv / (smt + EPS_DIV);
    u_s[tid] = 1.0f;
    v_s[tid] = 1.0f;
    __syncthreads();

    // ---- Phase 3: 100 Sinkhorn iterations -------------------------------
    for (int it = 0; it < MAX_IT; ++it) {
        // Kt_u[m]: thread m = tid walks column m.  K addr: n*SK + m (halves).
        {
            float s0 = 0.f, s1 = 0.f, s2 = 0.f, s3 = 0.f;
            #pragma unroll 4
            for (int n = 0; n < DIM; n += 4) {
                float4 uu = *(const float4*)(u_s + n);   // warp-uniform broadcast
                s0 = fmaf(__half2float(Kh[(n + 0) * SK + tid]), uu.x, s0);
                s1 = fmaf(__half2float(Kh[(n + 1) * SK + tid]), uu.y, s1);
                s2 = fmaf(__half2float(Kh[(n + 2) * SK + tid]), uu.z, s2);
                s3 = fmaf(__half2float(Kh[(n + 3) * SK + tid]), uu.w, s3);
            }
            float ktu = ((s0 + s1) + (s2 + s3)) * INV_KSCALE;
            v_s[tid] = b_s[tid] / (ktu + EPS_DIV);
        }
        __syncthreads();

        // K v: thread n = tid walks row n via 128-bit loads (8 halves each).
        {
            const uint4* Krow4 = (const uint4*)(Kh + tid * SK);  // 528B-aligned
            float t0 = 0.f, t1 = 0.f, t2 = 0.f, t3 = 0.f;
            #pragma unroll 4
            for (int j = 0; j < DIM / 8; ++j) {      // 32 iterations
                uint4 kq = Krow4[j];
                float4 va = *(const float4*)(v_s + 8 * j);
                float4 vb = *(const float4*)(v_s + 8 * j + 4);
                __half2 k0 = *(__half2*)&kq.x;
                __half2 k1 = *(__half2*)&kq.y;
                __half2 k2 = *(__half2*)&kq.z;
                __half2 k3 = *(__half2*)&kq.w;
                float2 f0 = __half22float2(k0);
                float2 f1 = __half22float2(k1);
                float2 f2 = __half22float2(k2);
                float2 f3 = __half22float2(k3);
                t0 = fmaf(f0.x, va.x, t0);
                t1 = fmaf(f0.y, va.y, t1);
                t2 = fmaf(f1.x, va.z, t2);
                t3 = fmaf(f1.y, va.w, t3);
                t0 = fmaf(f2.x, vb.x, t0);
                t1 = fmaf(f2.y, vb.y, t1);
                t2 = fmaf(f3.x, vb.z, t2);
                t3 = fmaf(f3.y, vb.w, t3);
            }
            float kv = ((t0 + t1) + (t2 + t3)) * INV_KSCALE;
            u_s[tid] = a_s[tid] / (kv + EPS_DIV);
        }
        __syncthreads();
    }

    // ---- Phase 4: cost = sum u[n] * exp(-10C)*C * v[m]  (exact fp32 K) --
    float acc = 0.f;
    for (int i = tid; i < (DIM * DIM / 4); i += 256) {
        float4 c = C4[i];
        int r   = i >> 6;
        int col = (i & 63) << 2;
        float ur = u_s[r];
        float p = __expf(-10.f * c.x) * c.x * v_s[col + 0]
                + __expf(-10.f * c.y) * c.y * v_s[col + 1]
                + __expf(-10.f * c.z) * c.z * v_s[col + 2]
                + __expf(-10.f * c.w) * c.w * v_s[col + 3];
        acc = fmaf(ur, p, acc);
    }
    float tot = block_sum256(acc, red, tid);
    if (tid == 0) g_partial[b] = tot;
}

extern "C" __global__ void __launch_bounds__(256)
reduce_kernel(float* __restrict__ out)
{
    __shared__ float red[8];
    int tid = threadIdx.x;
    float s = 0.f;
    #pragma unroll
    for (int i = 0; i < BATCH / 256; ++i)
        s += g_partial[tid + i * 256];
    #pragma unroll
    for (int o = 16; o > 0; o >>= 1)
        s += __shfl_xor_sync(0xffffffffu, s, o);
    if ((tid & 31) == 0) red[tid >> 5] = s;
    __syncthreads();
    if (tid == 0) {
        float total = 0.f;
        #pragma unroll
        for (int w = 0; w < 8; ++w) total += red[w];
        out[0] = total * (1.0f / (float)BATCH);
    }
}

extern "C" void kernel_launch(void* const* d_in, const int* in_sizes, int n_in,
                              void* d_out, int out_size)
{
    const float* C  = (const float*)d_in[0];   // [B,N,M]
    const float* mp = (const float*)d_in[1];   // [B,N]
    const float* mt = (const float*)d_in[2];   // [B,M]

    cudaFuncSetAttribute(sinkhorn_kernel,
                         cudaFuncAttributeMaxDynamicSharedMemorySize,
                         SMEM_BYTES);

    sinkhorn_kernel<<<BATCH, 256, SMEM_BYTES>>>(C, mp, mt);
    reduce_kernel<<<1, 256>>>((float*)d_out);
}

// round 5
// speedup vs baseline: 1.5453x; 1.5453x over previous
#include <cuda_runtime.h>
#include <cuda_fp16.h>

// Sinkhorn OT loss: B=1024, N=M=256, eps=0.1, 100 iters.
// One CTA per batch. K = exp(-10*C)*16 in SMEM fp16, pitch 264 halves
// (528 B/row): conflict-free for LDS.128 row walks AND half2 column walks.
// Both matvecs accumulate in fp16 (HFMA2, 4 split accumulators), with
// power-of-2 scales on K/u/v; divisions and final cost in fp32.
// Final cost pass recomputes exact fp32 K from C (cost is 2nd-order
// insensitive to u,v error at the Sinkhorn fixed point).

#define BATCH   1024
#define DIM     256
#define MAX_IT  100
#define EPS_DIV 1e-8f

#define SKH   264          // halves per K row (528 B)
#define SKH2  132          // half2 per K row

#define KSC_K 16.0f        // K stored as K*16
#define KSC_U 4.0f         // u_h stored as u*4
#define KSC_V 256.0f       // v_h stored as v*256
#define UNSC_KTU (1.0f/64.0f)     // 1/(16*4)
#define UNSC_KV  (1.0f/4096.0f)   // 1/(16*256)

#define K_BYTES   (DIM * SKH * 2)        // 135168
#define OFF_PART  (K_BYTES)              // float2[256]  = 2048 B
#define OFF_UH2   (OFF_PART + 2048)      // half2[256]   = 1024 B
#define OFF_VH2   (OFF_UH2 + 1024)       // half2[128]   =  512 B
#define OFF_US    (OFF_VH2 + 512)        // float[256]
#define OFF_VS    (OFF_US + 1024)        // float[256]
#define OFF_AS    (OFF_VS + 1024)        // float[256]
#define OFF_BS    (OFF_AS + 1024)        // float[256]
#define OFF_RED   (OFF_BS + 1024)        // float[8]
#define SMEM_BYTES (OFF_RED + 64)

__device__ float g_partial[BATCH];

__device__ __forceinline__ __half2 H2(unsigned int w) {
    return *reinterpret_cast<__half2*>(&w);
}

__device__ __forceinline__ float block_sum256(float val, float* red, int tid) {
    #pragma unroll
    for (int o = 16; o > 0; o >>= 1)
        val += __shfl_xor_sync(0xffffffffu, val, o);
    if ((tid & 31) == 0) red[tid >> 5] = val;
    __syncthreads();
    float total = 0.f;
    #pragma unroll
    for (int w = 0; w < 8; ++w) total += red[w];
    __syncthreads();
    return total;
}

extern "C" __global__ void __launch_bounds__(256)
sinkhorn_kernel(const float* __restrict__ C,
                const float* __restrict__ mp,
                const float* __restrict__ mt)
{
    extern __shared__ unsigned char smem[];
    __half*   Kh   = (__half*)smem;
    float2*   part = (float2*)(smem + OFF_PART);
    __half2*  u_h2 = (__half2*)(smem + OFF_UH2);
    __half2*  v_h2 = (__half2*)(smem + OFF_VH2);
    float*    u_s  = (float*)(smem + OFF_US);
    float*    v_s  = (float*)(smem + OFF_VS);
    float*    a_s  = (float*)(smem + OFF_AS);
    float*    b_s  = (float*)(smem + OFF_BS);
    float*    red  = (float*)(smem + OFF_RED);

    const int b   = blockIdx.x;
    const int tid = threadIdx.x;
    const float*  Cb = C + (size_t)b * (DIM * DIM);
    const float4* C4 = (const float4*)Cb;

    // ---- Phase 1: K = exp(-10C)*16 -> fp16 SMEM -------------------------
    for (int i = tid; i < (DIM * DIM / 4); i += 256) {
        float4 c = C4[i];
        int r   = i >> 6;
        int col = (i & 63) << 2;
        __half2* dst = (__half2*)(Kh + r * SKH + col);
        dst[0] = __floats2half2_rn(__expf(-10.f * c.x) * KSC_K,
                                   __expf(-10.f * c.y) * KSC_K);
        dst[1] = __floats2half2_rn(__expf(-10.f * c.z) * KSC_K,
                                   __expf(-10.f * c.w) * KSC_K);
    }

    // ---- Phase 2: normalize masses, init u ------------------------------
    float mpv = mp[b * DIM + tid];
    float mtv = mt[b * DIM + tid];
    __syncthreads();
    float smp = block_sum256(mpv, red, tid);
    float smt = block_sum256(mtv, red, tid);
    a_s[tid] = mpv / (smp + EPS_DIV);
    b_s[tid] = mtv / (smt + EPS_DIV);
    u_h2[tid] = __floats2half2_rn(KSC_U, KSC_U);   // u = 1
    __syncthreads();

    // ---- Phase 3: 100 Sinkhorn iterations -------------------------------
    const __half2* Kc    = (const __half2*)Kh;
    const uint4*   uq4   = (const uint4*)u_h2;      // 4 rows per load
    const uint4*   vq4   = (const uint4*)v_h2;      // 8 cols per load
    const uint4*   Krow4 = (const uint4*)(Kh + tid * SKH);

    const int c = tid & 127;     // column-pair index (cols 2c, 2c+1)
    const int h = tid >> 7;      // row-half: rows [h*128, h*128+128)

    for (int it = 0; it < MAX_IT; ++it) {
        // --- Kt_u: thread handles column pair c over its 128-row half ----
        {
            __half2 acc0 = __floats2half2_rn(0.f, 0.f);
            __half2 acc1 = acc0, acc2 = acc0, acc3 = acc0;
            const int base = h * 128;
            #pragma unroll 4
            for (int j = 0; j < 32; ++j) {
                int n = base + j * 4;
                uint4 uu = uq4[n >> 2];              // uniform broadcast
                acc0 = __hfma2(Kc[(n + 0) * SKH2 + c], H2(uu.x), acc0);
                acc1 = __hfma2(Kc[(n + 1) * SKH2 + c], H2(uu.y), acc1);
                acc2 = __hfma2(Kc[(n + 2) * SKH2 + c], H2(uu.z), acc2);
                acc3 = __hfma2(Kc[(n + 3) * SKH2 + c], H2(uu.w), acc3);
            }
            float2 f0 = __half22float2(acc0);
            float2 f1 = __half22float2(acc1);
            float2 f2 = __half22float2(acc2);
            float2 f3 = __half22float2(acc3);
            part[tid] = make_float2((f0.x + f1.x) + (f2.x + f3.x),
                                    (f0.y + f1.y) + (f2.y + f3.y));
        }
        __syncthreads();
        if (tid < 128) {
            float2 pa = part[tid];
            float2 pb = part[tid + 128];
            float ktu0 = (pa.x + pb.x) * UNSC_KTU;
            float ktu1 = (pa.y + pb.y) * UNSC_KTU;
            float v0 = b_s[2 * tid]     / (ktu0 + EPS_DIV);
            float v1 = b_s[2 * tid + 1] / (ktu1 + EPS_DIV);
            v_s[2 * tid]     = v0;
            v_s[2 * tid + 1] = v1;
            v_h2[tid] = __floats2half2_rn(v0 * KSC_V, v1 * KSC_V);
        }
        __syncthreads();

        // --- K v: thread walks its own row via LDS.128 -------------------
        {
            __half2 r0 = __floats2half2_rn(0.f, 0.f);
            __half2 r1 = r0, r2 = r0, r3 = r0;
            #pragma unroll 4
            for (int j = 0; j < 32; ++j) {
                uint4 kq = Krow4[j];
                uint4 vv = vq4[j];                   // uniform broadcast
                r0 = __hfma2(H2(kq.x), H2(vv.x), r0);
                r1 = __hfma2(H2(kq.y), H2(vv.y), r1);
                r2 = __hfma2(H2(kq.z), H2(vv.z), r2);
                r3 = __hfma2(H2(kq.w), H2(vv.w), r3);
            }
            float2 g0 = __half22float2(r0);
            float2 g1 = __half22float2(r1);
            float2 g2 = __half22float2(r2);
            float2 g3 = __half22float2(r3);
            float kv = (((g0.x + g0.y) + (g1.x + g1.y)) +
                        ((g2.x + g2.y) + (g3.x + g3.y))) * UNSC_KV;
            float u = a_s[tid] / (kv + EPS_DIV);
            u_s[tid] = u;
            u_h2[tid] = __floats2half2_rn(u * KSC_U, u * KSC_U);
        }
        __syncthreads();
    }

    // ---- Phase 4: cost = sum u[n] * exp(-10C)*C * v[m]  (exact fp32) ----
    float acc = 0.f;
    for (int i = tid; i < (DIM * DIM / 4); i += 256) {
        float4 c = C4[i];
        int r   = i >> 6;
        int col = (i & 63) << 2;
        float ur = u_s[r];
        float p = __expf(-10.f * c.x) * c.x * v_s[col + 0]
                + __expf(-10.f * c.y) * c.y * v_s[col + 1]
                + __expf(-10.f * c.z) * c.z * v_s[col + 2]
                + __expf(-10.f * c.w) * c.w * v_s[col + 3];
        acc = fmaf(ur, p, acc);
    }
    float tot = block_sum256(acc, red, tid);
    if (tid == 0) g_partial[b] = tot;
}

extern "C" __global__ void __launch_bounds__(256)
reduce_kernel(float* __restrict__ out)
{
    __shared__ float red[8];
    int tid = threadIdx.x;
    float s = 0.f;
    #pragma unroll
    for (int i = 0; i < BATCH / 256; ++i)
        s += g_partial[tid + i * 256];
    #pragma unroll
    for (int o = 16; o > 0; o >>= 1)
        s += __shfl_xor_sync(0xffffffffu, s, o);
    if ((tid & 31) == 0) red[tid >> 5] = s;
    __syncthreads();
    if (tid == 0) {
        float total = 0.f;
        #pragma unroll
        for (int w = 0; w < 8; ++w) total += red[w];
        out[0] = total * (1.0f / (float)BATCH);
    }
}

extern "C" void kernel_launch(void* const* d_in, const int* in_sizes, int n_in,
                              void* d_out, int out_size)
{
    const float* C  = (const float*)d_in[0];   // [B,N,M]
    const float* mp = (const float*)d_in[1];   // [B,N]
    const float* mt = (const float*)d_in[2];   // [B,M]

    cudaFuncSetAttribute(sinkhorn_kernel,
                         cudaFuncAttributeMaxDynamicSharedMemorySize,
                         SMEM_BYTES);

    sinkhorn_kernel<<<BATCH, 256, SMEM_BYTES>>>(C, mp, mt);
    reduce_kernel<<<1, 256>>>((float*)d_out);
}

// round 6
// speedup vs baseline: 1.5477x; 1.0016x over previous
#include <cuda_runtime.h>
#include <cuda_fp16.h>

// Sinkhorn OT loss: B=1024, N=M=256, eps=0.1, 100 iters.
// One CTA per batch. K = exp(-10*C)*16 in SMEM fp16, pitch 264 halves
// (528 B/row): conflict-free for LDS.128 row walks AND half2 column walks.
// Both matvecs accumulate in fp16 (HFMA2, 4 split accumulators), with
// power-of-2 scales on K/u/v; divisions and final cost in fp32.
// Final cost pass recomputes exact fp32 K from C (cost is 2nd-order
// insensitive to u,v error at the Sinkhorn fixed point).

#define BATCH   1024
#define DIM     256
#define MAX_IT  100
#define EPS_DIV 1e-8f

#define SKH   264          // halves per K row (528 B)
#define SKH2  132          // half2 per K row

#define KSC_K 16.0f        // K stored as K*16
#define KSC_U 4.0f         // u_h stored as u*4
#define KSC_V 256.0f       // v_h stored as v*256
#define UNSC_KTU (1.0f/64.0f)     // 1/(16*4)
#define UNSC_KV  (1.0f/4096.0f)   // 1/(16*256)

#define K_BYTES   (DIM * SKH * 2)        // 135168
#define OFF_PART  (K_BYTES)              // float2[256]  = 2048 B
#define OFF_UH2   (OFF_PART + 2048)      // half2[256]   = 1024 B
#define OFF_VH2   (OFF_UH2 + 1024)       // half2[128]   =  512 B
#define OFF_US    (OFF_VH2 + 512)        // float[256]
#define OFF_VS    (OFF_US + 1024)        // float[256]
#define OFF_AS    (OFF_VS + 1024)        // float[256]
#define OFF_BS    (OFF_AS + 1024)        // float[256]
#define OFF_RED   (OFF_BS + 1024)        // float[8]
#define SMEM_BYTES (OFF_RED + 64)

__device__ float g_partial[BATCH];

__device__ __forceinline__ __half2 H2(unsigned int w) {
    return *reinterpret_cast<__half2*>(&w);
}

__device__ __forceinline__ float block_sum256(float val, float* red, int tid) {
    #pragma unroll
    for (int o = 16; o > 0; o >>= 1)
        val += __shfl_xor_sync(0xffffffffu, val, o);
    if ((tid & 31) == 0) red[tid >> 5] = val;
    __syncthreads();
    float total = 0.f;
    #pragma unroll
    for (int w = 0; w < 8; ++w) total += red[w];
    __syncthreads();
    return total;
}

extern "C" __global__ void __launch_bounds__(256)
sinkhorn_kernel(const float* __restrict__ C,
                const float* __restrict__ mp,
                const float* __restrict__ mt)
{
    extern __shared__ unsigned char smem[];
    __half*   Kh   = (__half*)smem;
    float2*   part = (float2*)(smem + OFF_PART);
    __half2*  u_h2 = (__half2*)(smem + OFF_UH2);
    __half2*  v_h2 = (__half2*)(smem + OFF_VH2);
    float*    u_s  = (float*)(smem + OFF_US);
    float*    v_s  = (float*)(smem + OFF_VS);
    float*    a_s  = (float*)(smem + OFF_AS);
    float*    b_s  = (float*)(smem + OFF_BS);
    float*    red  = (float*)(smem + OFF_RED);

    const int b   = blockIdx.x;
    const int tid = threadIdx.x;
    const float*  Cb = C + (size_t)b * (DIM * DIM);
    const float4* C4 = (const float4*)Cb;

    // ---- Phase 1: K = exp(-10C)*16 -> fp16 SMEM -------------------------
    for (int i = tid; i < (DIM * DIM / 4); i += 256) {
        float4 c = C4[i];
        int r   = i >> 6;
        int col = (i & 63) << 2;
        __half2* dst = (__half2*)(Kh + r * SKH + col);
        dst[0] = __floats2half2_rn(__expf(-10.f * c.x) * KSC_K,
                                   __expf(-10.f * c.y) * KSC_K);
        dst[1] = __floats2half2_rn(__expf(-10.f * c.z) * KSC_K,
                                   __expf(-10.f * c.w) * KSC_K);
    }

    // ---- Phase 2: normalize masses, init u ------------------------------
    float mpv = mp[b * DIM + tid];
    float mtv = mt[b * DIM + tid];
    __syncthreads();
    float smp = block_sum256(mpv, red, tid);
    float smt = block_sum256(mtv, red, tid);
    a_s[tid] = mpv / (smp + EPS_DIV);
    b_s[tid] = mtv / (smt + EPS_DIV);
    u_h2[tid] = __floats2half2_rn(KSC_U, KSC_U);   // u = 1
    __syncthreads();

    // ---- Phase 3: 100 Sinkhorn iterations -------------------------------
    const __half2* Kc    = (const __half2*)Kh;
    const uint4*   uq4   = (const uint4*)u_h2;      // 4 rows per load
    const uint4*   vq4   = (const uint4*)v_h2;      // 8 cols per load
    const uint4*   Krow4 = (const uint4*)(Kh + tid * SKH);

    const int c = tid & 127;     // column-pair index (cols 2c, 2c+1)
    const int h = tid >> 7;      // row-half: rows [h*128, h*128+128)

    for (int it = 0; it < MAX_IT; ++it) {
        // --- Kt_u: thread handles column pair c over its 128-row half ----
        {
            __half2 acc0 = __floats2half2_rn(0.f, 0.f);
            __half2 acc1 = acc0, acc2 = acc0, acc3 = acc0;
            const int base = h * 128;
            #pragma unroll 4
            for (int j = 0; j < 32; ++j) {
                int n = base + j * 4;
                uint4 uu = uq4[n >> 2];              // uniform broadcast
                acc0 = __hfma2(Kc[(n + 0) * SKH2 + c], H2(uu.x), acc0);
                acc1 = __hfma2(Kc[(n + 1) * SKH2 + c], H2(uu.y), acc1);
                acc2 = __hfma2(Kc[(n + 2) * SKH2 + c], H2(uu.z), acc2);
                acc3 = __hfma2(Kc[(n + 3) * SKH2 + c], H2(uu.w), acc3);
            }
            float2 f0 = __half22float2(acc0);
            float2 f1 = __half22float2(acc1);
            float2 f2 = __half22float2(acc2);
            float2 f3 = __half22float2(acc3);
            part[tid] = make_float2((f0.x + f1.x) + (f2.x + f3.x),
                                    (f0.y + f1.y) + (f2.y + f3.y));
        }
        __syncthreads();
        if (tid < 128) {
            float2 pa = part[tid];
            float2 pb = part[tid + 128];
            float ktu0 = (pa.x + pb.x) * UNSC_KTU;
            float ktu1 = (pa.y + pb.y) * UNSC_KTU;
            float v0 = b_s[2 * tid]     / (ktu0 + EPS_DIV);
            float v1 = b_s[2 * tid + 1] / (ktu1 + EPS_DIV);
            v_s[2 * tid]     = v0;
            v_s[2 * tid + 1] = v1;
            v_h2[tid] = __floats2half2_rn(v0 * KSC_V, v1 * KSC_V);
        }
        __syncthreads();

        // --- K v: thread walks its own row via LDS.128 -------------------
        {
            __half2 r0 = __floats2half2_rn(0.f, 0.f);
            __half2 r1 = r0, r2 = r0, r3 = r0;
            #pragma unroll 4
            for (int j = 0; j < 32; ++j) {
                uint4 kq = Krow4[j];
                uint4 vv = vq4[j];                   // uniform broadcast
                r0 = __hfma2(H2(kq.x), H2(vv.x), r0);
                r1 = __hfma2(H2(kq.y), H2(vv.y), r1);
                r2 = __hfma2(H2(kq.z), H2(vv.z), r2);
                r3 = __hfma2(H2(kq.w), H2(vv.w), r3);
            }
            float2 g0 = __half22float2(r0);
            float2 g1 = __half22float2(r1);
            float2 g2 = __half22float2(r2);
            float2 g3 = __half22float2(r3);
            float kv = (((g0.x + g0.y) + (g1.x + g1.y)) +
                        ((g2.x + g2.y) + (g3.x + g3.y))) * UNSC_KV;
            float u = a_s[tid] / (kv + EPS_DIV);
            u_s[tid] = u;
            u_h2[tid] = __floats2half2_rn(u * KSC_U, u * KSC_U);
        }
        __syncthreads();
    }

    // ---- Phase 4: cost = sum u[n] * exp(-10C)*C * v[m]  (exact fp32) ----
    float acc = 0.f;
    for (int i = tid; i < (DIM * DIM / 4); i += 256) {
        float4 c = C4[i];
        int r   = i >> 6;
        int col = (i & 63) << 2;
        float ur = u_s[r];
        float p = __expf(-10.f * c.x) * c.x * v_s[col + 0]
                + __expf(-10.f * c.y) * c.y * v_s[col + 1]
                + __expf(-10.f * c.z) * c.z * v_s[col + 2]
                + __expf(-10.f * c.w) * c.w * v_s[col + 3];
        acc = fmaf(ur, p, acc);
    }
    float tot = block_sum256(acc, red, tid);
    if (tid == 0) g_partial[b] = tot;
}

extern "C" __global__ void __launch_bounds__(256)
reduce_kernel(float* __restrict__ out)
{
    __shared__ float red[8];
    int tid = threadIdx.x;
    float s = 0.f;
    #pragma unroll
    for (int i = 0; i < BATCH / 256; ++i)
        s += g_partial[tid + i * 256];
    #pragma unroll
    for (int o = 16; o > 0; o >>= 1)
        s += __shfl_xor_sync(0xffffffffu, s, o);
    if ((tid & 31) == 0) red[tid >> 5] = s;
    __syncthreads();
    if (tid == 0) {
        float total = 0.f;
        #pragma unroll
        for (int w = 0; w < 8; ++w) total += red[w];
        out[0] = total * (1.0f / (float)BATCH);
    }
}

extern "C" void kernel_launch(void* const* d_in, const int* in_sizes, int n_in,
                              void* d_out, int out_size)
{
    const float* C  = (const float*)d_in[0];   // [B,N,M]
    const float* mp = (const float*)d_in[1];   // [B,N]
    const float* mt = (const float*)d_in[2];   // [B,M]

    cudaFuncSetAttribute(sinkhorn_kernel,
                         cudaFuncAttributeMaxDynamicSharedMemorySize,
                         SMEM_BYTES);

    sinkhorn_kernel<<<BATCH, 256, SMEM_BYTES>>>(C, mp, mt);
    reduce_kernel<<<1, 256>>>((float*)d_out);
}